// round 3
// baseline (speedup 1.0000x reference)
#include <cuda_runtime.h>
#include <cstdint>

#define NN 16000
#define EE 512000
#define CC 32
#define SHD 9
#define NBAS 10
#define NLAYERS 3
#define NGRAPHS 40

// ---------------- device scratch (static globals; no runtime allocation) ----
__device__ float g_xt[NN * SHD * CC];        // x transposed: [n][k][c]   (18.4 MB)
__device__ float g_agg[NN * SHD * CC];       // aggregation buffer        (18.4 MB)
__device__ float g_w[(size_t)EE * CC];       // per-edge weights (layer-local, 65.5 MB)

// ---------------- helpers ---------------------------------------------------
__device__ __forceinline__ void red4(float4* p, float4 v) {
    asm volatile("red.global.add.v4.f32 [%0], {%1,%2,%3,%4};"
                 :: "l"(p), "f"(v.x), "f"(v.y), "f"(v.z), "f"(v.w)
                 : "memory");
}

__device__ __forceinline__ float fast_silu(float x) {
    return __fdividef(x, 1.0f + __expf(-x));
}

__device__ __forceinline__ void compute_sh(float vx, float vy, float vz,
                                           float* shv) {
    float r2 = vx * vx + vy * vy + vz * vz + 1e-12f;
    float rinv = rsqrtf(r2);
    float x = vx * rinv, y = vy * rinv, z = vz * rinv;
    const float s3    = 1.7320508075688772f;
    const float s15   = 3.872983346207417f;
    const float s5_4  = 1.118033988749895f;    // sqrt(5)/2
    const float s15_4 = 1.9364916731037085f;   // sqrt(15)/2
    shv[0] = 1.0f;
    shv[1] = s3 * x;
    shv[2] = s3 * y;
    shv[3] = s3 * z;
    shv[4] = s15 * x * y;
    shv[5] = s15 * y * z;
    shv[6] = s5_4 * (3.0f * z * z - 1.0f);
    shv[7] = s15 * z * x;
    shv[8] = s15_4 * (x * x - y * y);
}

// ---------------- kernel 1: transpose node_input into internal layout -------
__global__ void tin_kernel(const float* __restrict__ node_input) {
    int idx = blockIdx.x * blockDim.x + threadIdx.x;
    if (idx < NN * CC * SHD) {
        int n = idx / (CC * SHD);
        int r = idx % (CC * SHD);
        int c = r / SHD;
        int k = r % SHD;
        g_xt[(n * SHD + k) * CC + c] = node_input[idx];
    }
}

// ---------------- kernel 2: per-edge weight precompute for ONE layer --------
// One thread per edge. Weights for layer l staged in shared memory.
__global__ void edge_kernel(const float* __restrict__ edge_vec,
                            const float* __restrict__ edge_attr,
                            const float* __restrict__ W1,
                            const float* __restrict__ b1,
                            const float* __restrict__ W2,
                            const float* __restrict__ Wattr,
                            int l) {
    __shared__ float sW1t[100 * 12];   // [j][i], i padded to 12
    __shared__ float sW2[100 * 32];    // [j][c]
    __shared__ float sWattr[13 * 32];  // [i][c]
    __shared__ float sb1[100];

    const int tid = threadIdx.x;
    const int e = blockIdx.x * blockDim.x + tid;

    for (int idx = tid; idx < 1000; idx += blockDim.x) {
        int i = idx / 100, j = idx % 100;
        sW1t[j * 12 + i] = W1[l * 1000 + idx];
    }
    if (tid < 200) sW1t[(tid >> 1) * 12 + 10 + (tid & 1)] = 0.0f;  // pad
    for (int idx = tid; idx < 3200; idx += blockDim.x) sW2[idx] = W2[l * 3200 + idx];
    for (int idx = tid; idx < 416; idx += blockDim.x) sWattr[idx] = Wattr[l * 416 + idx];
    if (tid < 100) sb1[tid] = b1[l * 100 + tid];
    __syncthreads();

    if (e >= EE) return;

    float vx = edge_vec[3 * e + 0];
    float vy = edge_vec[3 * e + 1];
    float vz = edge_vec[3 * e + 2];
    float d = sqrtf(vx * vx + vy * vy + vz * vz + 1e-12f);

    float shv[9];
    compute_sh(vx, vy, vz, shv);

    float ea[13];
    ea[0] = edge_attr[4 * e + 0];
    ea[1] = edge_attr[4 * e + 1];
    ea[2] = edge_attr[4 * e + 2];
    ea[3] = edge_attr[4 * e + 3];
    #pragma unroll
    for (int k = 0; k < 9; k++) ea[4 + k] = shv[k];

    // radial basis: centers at (5/11)*(i+1), step 5/11, strict window
    float emb[10];
    {
        const float stepinv = 11.0f / 5.0f;
        const float SQNB = 3.1622776601683795f;   // sqrt(10)
        const float HPI = 1.5707963267948966f;
        #pragma unroll
        for (int i = 0; i < 10; i++) {
            float center = (5.0f / 11.0f) * (float)(i + 1);
            float diff = (d - center) * stepinv;
            float v = 0.0f;
            if (diff > -1.0f && diff < 1.0f) v = __cosf(HPI * diff) * SQNB;
            emb[i] = v;
        }
    }

    float w[32];
    #pragma unroll
    for (int c = 0; c < 32; c++) w[c] = 0.0f;

    for (int j = 0; j < 100; j++) {
        const float4* r1 = (const float4*)&sW1t[j * 12];
        float4 A = r1[0], B = r1[1], Cc = r1[2];
        float hj = sb1[j]
            + emb[0] * A.x + emb[1] * A.y + emb[2] * A.z + emb[3] * A.w
            + emb[4] * B.x + emb[5] * B.y + emb[6] * B.z + emb[7] * B.w
            + emb[8] * Cc.x + emb[9] * Cc.y;
        hj = fast_silu(hj);
        const float4* r2p = (const float4*)&sW2[j * 32];
        #pragma unroll
        for (int q = 0; q < 8; q++) {
            float4 ww = r2p[q];
            w[4 * q + 0] += hj * ww.x;
            w[4 * q + 1] += hj * ww.y;
            w[4 * q + 2] += hj * ww.z;
            w[4 * q + 3] += hj * ww.w;
        }
    }

    // multiply by (ea @ Wattr) and fold 1/sqrt(32)
    const float INVS32 = 0.17677669529663687f;
    float4* outp4 = (float4*)(g_w + (size_t)e * 32);
    #pragma unroll
    for (int q = 0; q < 8; q++) {
        float aw0 = 0.f, aw1 = 0.f, aw2 = 0.f, aw3 = 0.f;
        #pragma unroll
        for (int i = 0; i < 13; i++) {
            const float* wa = &sWattr[i * 32 + 4 * q];
            float ei = ea[i];
            aw0 += ei * wa[0];
            aw1 += ei * wa[1];
            aw2 += ei * wa[2];
            aw3 += ei * wa[3];
        }
        float4 o;
        o.x = w[4 * q + 0] * aw0 * INVS32;
        o.y = w[4 * q + 1] * aw1 * INVS32;
        o.z = w[4 * q + 2] * aw2 * INVS32;
        o.w = w[4 * q + 3] * aw3 * INVS32;
        outp4[q] = o;
    }
}

// ---------------- kernel 3: zero buffers -------------------------------------
__global__ void zero_kernel(float* __restrict__ p, int n) {
    int i = blockIdx.x * blockDim.x + threadIdx.x;
    if (i < n) p[i] = 0.0f;
}

__global__ void zero_agg_kernel() {
    int i = blockIdx.x * blockDim.x + threadIdx.x;
    if (i < NN * SHD * CC) g_agg[i] = 0.0f;
}

// ---------------- kernel 4: message + scatter (one warp per edge) -----------
// sh recomputed from edge_vec (12B/edge) instead of a cached buffer (36B/edge).
__global__ void msg_kernel(const int* __restrict__ eidx,
                           const float* __restrict__ edge_vec) {
    int warp = threadIdx.x >> 5;
    int lane = threadIdx.x & 31;
    int e = blockIdx.x * 8 + warp;
    int dst = eidx[e];
    int src = eidx[EE + e];
    int c4 = lane & 7;
    int kb = lane >> 3;

    // lanes 0..2 load vec components; broadcast
    float vx = __shfl_sync(0xffffffffu, (lane < 3) ? edge_vec[3 * e + lane] : 0.0f, 0 + 0);
    // note: need separate broadcasts:
    float vcomp = (lane < 3) ? edge_vec[3 * e + lane] : 0.0f;
    vx = __shfl_sync(0xffffffffu, vcomp, 0);
    float vy = __shfl_sync(0xffffffffu, vcomp, 1);
    float vz = __shfl_sync(0xffffffffu, vcomp, 2);

    float shv[9];
    compute_sh(vx, vy, vz, shv);

    const float4* wrow = (const float4*)(g_w + (size_t)e * 32);
    float4 w4 = wrow[c4];
    const float4* xs = ((const float4*)g_xt) + (size_t)src * 72;  // 9*8 float4/node
    float4* ag = ((float4*)g_agg) + (size_t)dst * 72;

    #pragma unroll
    for (int p = 0; p < 3; p++) {
        int k = kb + 4 * p;
        if (k < 9) {
            float s = shv[k];
            float4 xv = xs[k * 8 + c4];
            float4 v;
            v.x = xv.x * s * w4.x;
            v.y = xv.y * s * w4.y;
            v.z = xv.z * s * w4.z;
            v.w = xv.w * s * w4.w;
            red4(ag + k * 8 + c4, v);
        }
    }
}

// ---------------- kernel 5: node update (self + out mix, gating) ------------
// One block per node, 288 threads = 9 warps (k) x 32 lanes (d).
__global__ void node_kernel(const float* __restrict__ node_attr,
                            const float* __restrict__ Wself,
                            const float* __restrict__ Wout, int l) {
    __shared__ float sWs[1024], sWo[1024];
    __shared__ float sx[9][32], sa[9][32], sv[9][32];
    int t = threadIdx.x;
    for (int i = t; i < 1024; i += 288) {
        sWs[i] = Wself[l * 1024 + i];
        sWo[i] = Wout[l * 1024 + i];
    }
    int n = blockIdx.x;
    int k = t >> 5;
    int d = t & 31;
    sx[k][d] = g_xt[(n * SHD + k) * CC + d];
    sa[k][d] = g_agg[(n * SHD + k) * CC + d];
    __syncthreads();

    float accS = 0.0f, accA = 0.0f;
    #pragma unroll
    for (int c = 0; c < 32; c++) {
        accS += sx[k][c] * sWs[c * 32 + d];
        accA += sa[k][c] * sWo[c * 32 + d];
    }
    float val = node_attr[n] * accS + accA;
    sv[k][d] = val;
    __syncthreads();

    float s = sv[0][d];
    float sig = __fdividef(1.0f, 1.0f + __expf(-s));
    float res = (k == 0) ? s * sig : val * sig;
    g_xt[(n * SHD + k) * CC + d] = res;
}

// ---------------- kernel 6: graph-level segment sum (batch is sorted) -------
__global__ void out_kernel(const int* __restrict__ batch, float* __restrict__ out) {
    int t = threadIdx.x;        // 288 threads: output element (c,k)
    int c = t / 9;
    int k = t % 9;
    int n0 = blockIdx.x * 128;
    int n1 = n0 + 128;
    if (n1 > NN) n1 = NN;
    float acc = 0.0f;
    int curg = batch[n0];
    const float INVS400 = 0.05f;  // 1/sqrt(400)
    for (int n = n0; n < n1; n++) {
        int g = batch[n];
        if (g != curg) {
            atomicAdd(&out[curg * 288 + c * 9 + k], acc * INVS400);
            acc = 0.0f;
            curg = g;
        }
        acc += g_xt[(n * SHD + k) * CC + c];
    }
    atomicAdd(&out[curg * 288 + c * 9 + k], acc * INVS400);
}

// ---------------- launch ----------------------------------------------------
extern "C" void kernel_launch(void* const* d_in, const int* in_sizes, int n_in,
                              void* d_out, int out_size) {
    const float* node_input = (const float*)d_in[0];
    const float* node_attr  = (const float*)d_in[1];
    const float* edge_vec   = (const float*)d_in[2];
    const float* edge_attr  = (const float*)d_in[3];
    const float* W1         = (const float*)d_in[4];
    const float* b1         = (const float*)d_in[5];
    const float* W2         = (const float*)d_in[6];
    const float* Wattr      = (const float*)d_in[7];
    const float* Wself      = (const float*)d_in[8];
    const float* Wout       = (const float*)d_in[9];
    const int*   eidx       = (const int*)d_in[10];
    const int*   batch      = (const int*)d_in[11];
    float* out = (float*)d_out;

    {
        int n = NN * CC * SHD;
        tin_kernel<<<(n + 255) / 256, 256>>>(node_input);
    }

    for (int l = 0; l < NLAYERS; l++) {
        edge_kernel<<<EE / 256, 256>>>(edge_vec, edge_attr, W1, b1, W2, Wattr, l);
        {
            int n = NN * SHD * CC;
            zero_agg_kernel<<<(n + 255) / 256, 256>>>();
        }
        msg_kernel<<<EE / 8, 256>>>(eidx, edge_vec);
        node_kernel<<<NN, 288>>>(node_attr, Wself, Wout, l);
    }

    zero_kernel<<<(out_size + 255) / 256, 256>>>(out, out_size);
    out_kernel<<<(NN + 127) / 128, 288>>>(batch, out);
}

// round 4
// speedup vs baseline: 1.1189x; 1.1189x over previous
#include <cuda_runtime.h>
#include <cstdint>

#define NN 16000
#define EE 512000
#define CC 32
#define SHD 9
#define NLAYERS 3
#define NGRAPHS 40

// ---------------- device scratch --------------------------------------------
__device__ float g_xt[NN * SHD * CC];        // x: [n][k][c]              (18.4 MB)
__device__ float g_agg[NN * SHD * CC];       // aggregated messages       (18.4 MB)
__device__ float g_w[(size_t)EE * CC];       // per-edge weights          (65.5 MB)
__device__ float g_sh[EE * SHD];             // spherical harmonics       (18.4 MB)
__device__ int   g_cnt[NN];
__device__ int   g_off[NN + 1];
__device__ int   g_cur[NN];
__device__ int   g_perm[EE];

// ---------------- helpers ---------------------------------------------------
__device__ __forceinline__ float fast_silu(float x) {
    return __fdividef(x, 1.0f + __expf(-x));
}

__device__ __forceinline__ void compute_sh(float vx, float vy, float vz, float* shv) {
    float r2 = vx * vx + vy * vy + vz * vz + 1e-12f;
    float rinv = rsqrtf(r2);
    float x = vx * rinv, y = vy * rinv, z = vz * rinv;
    const float s3    = 1.7320508075688772f;
    const float s15   = 3.872983346207417f;
    const float s5_4  = 1.118033988749895f;    // sqrt(5)/2
    const float s15_4 = 1.9364916731037085f;   // sqrt(15)/2
    shv[0] = 1.0f;
    shv[1] = s3 * x;
    shv[2] = s3 * y;
    shv[3] = s3 * z;
    shv[4] = s15 * x * y;
    shv[5] = s15 * y * z;
    shv[6] = s5_4 * (3.0f * z * z - 1.0f);
    shv[7] = s15 * z * x;
    shv[8] = s15_4 * (x * x - y * y);
}

// ---------------- kernel: transpose node_input ------------------------------
__global__ void tin_kernel(const float* __restrict__ node_input) {
    int idx = blockIdx.x * blockDim.x + threadIdx.x;
    if (idx < NN * CC * SHD) {
        int n = idx / (CC * SHD);
        int r = idx % (CC * SHD);
        int c = r / SHD;
        int k = r % SHD;
        g_xt[(n * SHD + k) * CC + c] = node_input[idx];
    }
}

// ---------------- sort-by-dst pipeline --------------------------------------
__global__ void zero_cnt_kernel() {
    int i = blockIdx.x * blockDim.x + threadIdx.x;
    if (i < NN) g_cnt[i] = 0;
}

__global__ void hist_kernel(const int* __restrict__ eidx) {
    int e = blockIdx.x * blockDim.x + threadIdx.x;
    if (e < EE) atomicAdd(&g_cnt[eidx[e]], 1);
}

__global__ void scan_kernel() {
    __shared__ int sdata[1024];
    __shared__ int s_carry;
    int tid = threadIdx.x;
    if (tid == 0) s_carry = 0;
    __syncthreads();
    for (int base = 0; base < NN; base += 1024) {
        int i = base + tid;
        int v = (i < NN) ? g_cnt[i] : 0;
        sdata[tid] = v;
        __syncthreads();
        #pragma unroll
        for (int ofs = 1; ofs < 1024; ofs <<= 1) {
            int t = (tid >= ofs) ? sdata[tid - ofs] : 0;
            __syncthreads();
            sdata[tid] += t;
            __syncthreads();
        }
        int excl = sdata[tid] - v + s_carry;
        if (i < NN) { g_off[i] = excl; g_cur[i] = excl; }
        __syncthreads();
        if (tid == 1023) s_carry += sdata[1023];
        __syncthreads();
    }
    if (tid == 0) g_off[NN] = EE;
}

__global__ void scatter_kernel(const int* __restrict__ eidx) {
    int e = blockIdx.x * blockDim.x + threadIdx.x;
    if (e < EE) {
        int d = eidx[e];
        int pos = atomicAdd(&g_cur[d], 1);
        g_perm[pos] = e;
    }
}

// ---------------- kernel: per-edge weights, 2 edges per thread --------------
__device__ __forceinline__ void edge_pre(int e, int l,
                                         const float* __restrict__ edge_vec,
                                         const float* __restrict__ edge_attr,
                                         float* emb, float* shv, float* at) {
    float vx = edge_vec[3 * e + 0];
    float vy = edge_vec[3 * e + 1];
    float vz = edge_vec[3 * e + 2];
    float d = sqrtf(vx * vx + vy * vy + vz * vz + 1e-12f);
    compute_sh(vx, vy, vz, shv);
    if (l == 0) {
        #pragma unroll
        for (int k = 0; k < 9; k++) g_sh[e * 9 + k] = shv[k];
    }
    at[0] = edge_attr[4 * e + 0];
    at[1] = edge_attr[4 * e + 1];
    at[2] = edge_attr[4 * e + 2];
    at[3] = edge_attr[4 * e + 3];
    const float stepinv = 11.0f / 5.0f;
    const float SQNB = 3.1622776601683795f;   // sqrt(10)
    const float HPI = 1.5707963267948966f;
    #pragma unroll
    for (int i = 0; i < 10; i++) {
        float center = (5.0f / 11.0f) * (float)(i + 1);
        float diff = (d - center) * stepinv;
        float v = 0.0f;
        if (diff > -1.0f && diff < 1.0f) v = __cosf(HPI * diff) * SQNB;
        emb[i] = v;
    }
}

__device__ __forceinline__ void edge_post(int e, const float* shv, const float* at,
                                          const float* w, const float* sWattr) {
    float ea[13];
    ea[0] = at[0]; ea[1] = at[1]; ea[2] = at[2]; ea[3] = at[3];
    #pragma unroll
    for (int k = 0; k < 9; k++) ea[4 + k] = shv[k];
    const float INVS32 = 0.17677669529663687f;   // 1/sqrt(32)
    float4* outp4 = (float4*)(g_w + (size_t)e * 32);
    #pragma unroll
    for (int q = 0; q < 8; q++) {
        float aw0 = 0.f, aw1 = 0.f, aw2 = 0.f, aw3 = 0.f;
        #pragma unroll
        for (int i = 0; i < 13; i++) {
            const float* wa = &sWattr[i * 32 + 4 * q];
            float ei = ea[i];
            aw0 += ei * wa[0];
            aw1 += ei * wa[1];
            aw2 += ei * wa[2];
            aw3 += ei * wa[3];
        }
        float4 o;
        o.x = w[4 * q + 0] * aw0 * INVS32;
        o.y = w[4 * q + 1] * aw1 * INVS32;
        o.z = w[4 * q + 2] * aw2 * INVS32;
        o.w = w[4 * q + 3] * aw3 * INVS32;
        outp4[q] = o;
    }
}

__global__ __launch_bounds__(128) void edge_kernel(
        const float* __restrict__ edge_vec,
        const float* __restrict__ edge_attr,
        const float* __restrict__ W1,
        const float* __restrict__ b1,
        const float* __restrict__ W2,
        const float* __restrict__ Wattr,
        int l) {
    __shared__ float sW1t[100 * 12];   // [j][i], i padded to 12
    __shared__ float sW2[100 * 32];    // [j][c]
    __shared__ float sWattr[13 * 32];  // [i][c]
    __shared__ float sb1[100];

    const int tid = threadIdx.x;
    for (int idx = tid; idx < 1000; idx += 128) {
        int i = idx / 100, j = idx % 100;
        sW1t[j * 12 + i] = W1[l * 1000 + idx];
    }
    for (int idx = tid; idx < 200; idx += 128)
        sW1t[(idx >> 1) * 12 + 10 + (idx & 1)] = 0.0f;
    for (int idx = tid; idx < 3200; idx += 128) sW2[idx] = W2[l * 3200 + idx];
    for (int idx = tid; idx < 416; idx += 128) sWattr[idx] = Wattr[l * 416 + idx];
    if (tid < 100) sb1[tid] = b1[l * 100 + tid];
    __syncthreads();

    const int e0 = blockIdx.x * 256 + tid;
    const int e1 = e0 + 128;

    float emb0[10], shv0[9], at0[4];
    float emb1[10], shv1[9], at1[4];
    edge_pre(e0, l, edge_vec, edge_attr, emb0, shv0, at0);
    edge_pre(e1, l, edge_vec, edge_attr, emb1, shv1, at1);

    float w0[32], w1[32];
    #pragma unroll
    for (int c = 0; c < 32; c++) { w0[c] = 0.0f; w1[c] = 0.0f; }

    for (int j = 0; j < 100; j++) {
        const float4* r1 = (const float4*)&sW1t[j * 12];
        float4 A = r1[0], B = r1[1], Cc = r1[2];
        float bj = sb1[j];
        float h0 = bj
            + emb0[0] * A.x + emb0[1] * A.y + emb0[2] * A.z + emb0[3] * A.w
            + emb0[4] * B.x + emb0[5] * B.y + emb0[6] * B.z + emb0[7] * B.w
            + emb0[8] * Cc.x + emb0[9] * Cc.y;
        float h1 = bj
            + emb1[0] * A.x + emb1[1] * A.y + emb1[2] * A.z + emb1[3] * A.w
            + emb1[4] * B.x + emb1[5] * B.y + emb1[6] * B.z + emb1[7] * B.w
            + emb1[8] * Cc.x + emb1[9] * Cc.y;
        h0 = fast_silu(h0);
        h1 = fast_silu(h1);
        const float4* r2p = (const float4*)&sW2[j * 32];
        #pragma unroll
        for (int q = 0; q < 8; q++) {
            float4 ww = r2p[q];
            w0[4 * q + 0] += h0 * ww.x;
            w0[4 * q + 1] += h0 * ww.y;
            w0[4 * q + 2] += h0 * ww.z;
            w0[4 * q + 3] += h0 * ww.w;
            w1[4 * q + 0] += h1 * ww.x;
            w1[4 * q + 1] += h1 * ww.y;
            w1[4 * q + 2] += h1 * ww.z;
            w1[4 * q + 3] += h1 * ww.w;
        }
    }

    edge_post(e0, shv0, at0, w0, sWattr);
    edge_post(e1, shv1, at1, w1, sWattr);
}

// ---------------- kernel: gather-aggregate (sorted, no atomics) -------------
// 288 threads = 4 nodes x 72 threads (9 k x 8 c4). Register accumulation.
__global__ __launch_bounds__(288) void agg_kernel(const int* __restrict__ eidx) {
    int t = threadIdx.x;
    int sub = t / 72;
    int r = t - sub * 72;
    int k = r >> 3;
    int c4 = r & 7;
    int n = blockIdx.x * 4 + sub;

    int j0 = g_off[n];
    int j1 = g_off[n + 1];
    float4 acc = make_float4(0.f, 0.f, 0.f, 0.f);

    #pragma unroll 2
    for (int j = j0; j < j1; j++) {
        int e = g_perm[j];
        int src = eidx[EE + e];
        float s = g_sh[e * 9 + k];
        float4 w4 = *(const float4*)(g_w + (size_t)e * 32 + c4 * 4);
        float4 xv = *(const float4*)(g_xt + (size_t)src * 288 + k * 32 + c4 * 4);
        acc.x = fmaf(xv.x, s * w4.x, acc.x);
        acc.y = fmaf(xv.y, s * w4.y, acc.y);
        acc.z = fmaf(xv.z, s * w4.z, acc.z);
        acc.w = fmaf(xv.w, s * w4.w, acc.w);
    }
    *(float4*)(g_agg + (size_t)n * 288 + k * 32 + c4 * 4) = acc;
}

// ---------------- kernel: node update (self + out mix, gating) --------------
__global__ void node_kernel(const float* __restrict__ node_attr,
                            const float* __restrict__ Wself,
                            const float* __restrict__ Wout, int l) {
    __shared__ float sWs[1024], sWo[1024];
    __shared__ float sx[9][32], sa[9][32], sv[9][32];
    int t = threadIdx.x;
    for (int i = t; i < 1024; i += 288) {
        sWs[i] = Wself[l * 1024 + i];
        sWo[i] = Wout[l * 1024 + i];
    }
    int n = blockIdx.x;
    int k = t >> 5;
    int d = t & 31;
    sx[k][d] = g_xt[(n * SHD + k) * CC + d];
    sa[k][d] = g_agg[(n * SHD + k) * CC + d];
    __syncthreads();

    float accS = 0.0f, accA = 0.0f;
    #pragma unroll
    for (int c = 0; c < 32; c++) {
        accS += sx[k][c] * sWs[c * 32 + d];
        accA += sa[k][c] * sWo[c * 32 + d];
    }
    float val = node_attr[n] * accS + accA;
    sv[k][d] = val;
    __syncthreads();

    float s = sv[0][d];
    float sig = __fdividef(1.0f, 1.0f + __expf(-s));
    float res = (k == 0) ? s * sig : val * sig;
    g_xt[(n * SHD + k) * CC + d] = res;
}

// ---------------- output reduction ------------------------------------------
__global__ void zero_kernel(float* __restrict__ p, int n) {
    int i = blockIdx.x * blockDim.x + threadIdx.x;
    if (i < n) p[i] = 0.0f;
}

__global__ void out_kernel(const int* __restrict__ batch, float* __restrict__ out) {
    int t = threadIdx.x;        // 288 threads: output element (c,k)
    int c = t / 9;
    int k = t % 9;
    int n0 = blockIdx.x * 64;
    int n1 = n0 + 64;
    if (n1 > NN) n1 = NN;
    float acc = 0.0f;
    int curg = batch[n0];
    const float INVS400 = 0.05f;  // 1/sqrt(400)
    for (int n = n0; n < n1; n++) {
        int g = batch[n];
        if (g != curg) {
            atomicAdd(&out[curg * 288 + c * 9 + k], acc * INVS400);
            acc = 0.0f;
            curg = g;
        }
        acc += g_xt[(n * SHD + k) * CC + c];
    }
    atomicAdd(&out[curg * 288 + c * 9 + k], acc * INVS400);
}

// ---------------- launch ----------------------------------------------------
extern "C" void kernel_launch(void* const* d_in, const int* in_sizes, int n_in,
                              void* d_out, int out_size) {
    const float* node_input = (const float*)d_in[0];
    const float* node_attr  = (const float*)d_in[1];
    const float* edge_vec   = (const float*)d_in[2];
    const float* edge_attr  = (const float*)d_in[3];
    const float* W1         = (const float*)d_in[4];
    const float* b1         = (const float*)d_in[5];
    const float* W2         = (const float*)d_in[6];
    const float* Wattr      = (const float*)d_in[7];
    const float* Wself      = (const float*)d_in[8];
    const float* Wout       = (const float*)d_in[9];
    const int*   eidx       = (const int*)d_in[10];
    const int*   batch      = (const int*)d_in[11];
    float* out = (float*)d_out;

    {
        int n = NN * CC * SHD;
        tin_kernel<<<(n + 255) / 256, 256>>>(node_input);
    }

    // sort edges by destination (once per launch)
    zero_cnt_kernel<<<(NN + 255) / 256, 256>>>();
    hist_kernel<<<EE / 256, 256>>>(eidx);
    scan_kernel<<<1, 1024>>>();
    scatter_kernel<<<EE / 256, 256>>>(eidx);

    for (int l = 0; l < NLAYERS; l++) {
        edge_kernel<<<EE / 256, 128>>>(edge_vec, edge_attr, W1, b1, W2, Wattr, l);
        agg_kernel<<<NN / 4, 288>>>(eidx);
        node_kernel<<<NN, 288>>>(node_attr, Wself, Wout, l);
    }

    zero_kernel<<<(out_size + 255) / 256, 256>>>(out, out_size);
    out_kernel<<<(NN + 63) / 64, 288>>>(batch, out);
}

// round 6
// speedup vs baseline: 1.1816x; 1.0560x over previous
#include <cuda_runtime.h>
#include <cstdint>

#define NN 16000
#define EE 512000
#define CC 32
#define SHD 9
#define NLAYERS 3
#define NGRAPHS 40
#define TBINS 2200          // bins over [0,5]; knots 5k/11 align at i=200k
#define TSCALE 440.0f       // TBINS/5

// ---------------- device scratch --------------------------------------------
__device__ float g_bufA[NN * SHD * CC];                  // node state ping (18.4 MB)
__device__ float g_bufB[NN * SHD * CC];                  // node state pong (18.4 MB)
__device__ float g_w[(size_t)EE * CC];                   // per-edge weights (65.5 MB)
__device__ float g_sh[EE * SHD];                         // sph harmonics (18.4 MB)
__device__ float g_tab[NLAYERS * (TBINS + 1) * CC];      // radial tables (0.85 MB)
__device__ int   g_cnt[NN];
__device__ int   g_off[NN + 1];
__device__ int   g_cur[NN];
__device__ int   g_perm[EE];
__device__ int   g_bsum[16];

// ---------------- helpers ---------------------------------------------------
__device__ __forceinline__ float fast_silu(float x) {
    return __fdividef(x, 1.0f + __expf(-x));
}

__device__ __forceinline__ void compute_sh(float vx, float vy, float vz, float* shv) {
    float r2 = vx * vx + vy * vy + vz * vz + 1e-12f;
    float rinv = rsqrtf(r2);
    float x = vx * rinv, y = vy * rinv, z = vz * rinv;
    const float s3    = 1.7320508075688772f;
    const float s15   = 3.872983346207417f;
    const float s5_4  = 1.118033988749895f;    // sqrt(5)/2
    const float s15_4 = 1.9364916731037085f;   // sqrt(15)/2
    shv[0] = 1.0f;
    shv[1] = s3 * x;
    shv[2] = s3 * y;
    shv[3] = s3 * z;
    shv[4] = s15 * x * y;
    shv[5] = s15 * y * z;
    shv[6] = s5_4 * (3.0f * z * z - 1.0f);
    shv[7] = s15 * z * x;
    shv[8] = s15_4 * (x * x - y * y);
}

__device__ __forceinline__ void compute_emb(float d, float* emb) {
    const float stepinv = 11.0f / 5.0f;
    const float SQNB = 3.1622776601683795f;   // sqrt(10)
    const float HPI = 1.5707963267948966f;
    #pragma unroll
    for (int i = 0; i < 10; i++) {
        float center = (5.0f / 11.0f) * (float)(i + 1);
        float diff = (d - center) * stepinv;
        float v = 0.0f;
        if (diff > -1.0f && diff < 1.0f) v = __cosf(HPI * diff) * SQNB;
        emb[i] = v;
    }
}

// ---------------- kernel: transpose node_input ------------------------------
__global__ void tin_kernel(const float* __restrict__ node_input) {
    int idx = blockIdx.x * blockDim.x + threadIdx.x;
    if (idx < NN * CC * SHD) {
        int n = idx / (CC * SHD);
        int r = idx % (CC * SHD);
        int c = r / SHD;
        int k = r % SHD;
        g_bufA[(n * SHD + k) * CC + c] = node_input[idx];
    }
}

// ---------------- radial table build (all layers) ---------------------------
__global__ void tab_kernel(const float* __restrict__ W1,
                           const float* __restrict__ b1,
                           const float* __restrict__ W2) {
    int bin = blockIdx.x * blockDim.x + threadIdx.x;
    int l = blockIdx.y;
    if (bin > TBINS) return;
    float d = (float)bin * (5.0f / (float)TBINS);
    float emb[10];
    compute_emb(d, emb);
    float w[32];
    #pragma unroll
    for (int c = 0; c < 32; c++) w[c] = 0.0f;
    for (int j = 0; j < 100; j++) {
        float h = b1[l * 100 + j];
        #pragma unroll
        for (int i = 0; i < 10; i++) h += emb[i] * W1[l * 1000 + i * 100 + j];
        h = fast_silu(h);
        const float* w2r = &W2[l * 3200 + j * 32];
        #pragma unroll
        for (int c = 0; c < 32; c++) w[c] += h * w2r[c];
    }
    const float INVS32 = 0.17677669529663687f;  // fold 1/sqrt(32)
    float* out = &g_tab[((size_t)l * (TBINS + 1) + bin) * 32];
    #pragma unroll
    for (int c = 0; c < 32; c++) out[c] = w[c] * INVS32;
}

// ---------------- sort-by-dst pipeline --------------------------------------
__global__ void zero_cnt_kernel() {
    int i = blockIdx.x * blockDim.x + threadIdx.x;
    if (i < NN) g_cnt[i] = 0;
}

__global__ void hist_kernel(const int* __restrict__ eidx) {
    int e = blockIdx.x * blockDim.x + threadIdx.x;
    if (e < EE) atomicAdd(&g_cnt[eidx[e]], 1);
}

__global__ void scan1_kernel() {
    __shared__ int wsum[32];
    int tid = threadIdx.x;
    int b = blockIdx.x;
    int i = b * 1024 + tid;
    int v = (i < NN) ? g_cnt[i] : 0;
    int lane = tid & 31, wid = tid >> 5;
    int x = v;
    #pragma unroll
    for (int o = 1; o < 32; o <<= 1) {
        int t = __shfl_up_sync(0xffffffffu, x, o);
        if (lane >= o) x += t;
    }
    if (lane == 31) wsum[wid] = x;
    __syncthreads();
    if (wid == 0) {
        int y = wsum[lane];
        #pragma unroll
        for (int o = 1; o < 32; o <<= 1) {
            int t = __shfl_up_sync(0xffffffffu, y, o);
            if (lane >= o) y += t;
        }
        wsum[lane] = y;
    }
    __syncthreads();
    int incl = x + ((wid > 0) ? wsum[wid - 1] : 0);
    if (i < NN) g_off[i] = incl - v;
    if (tid == 1023) g_bsum[b] = incl;
}

__global__ void scan2_kernel() {
    int tid = threadIdx.x;
    int v = (tid < 16) ? g_bsum[tid] : 0;
    int x = v;
    #pragma unroll
    for (int o = 1; o < 32; o <<= 1) {
        int t = __shfl_up_sync(0xffffffffu, x, o);
        if (tid >= o) x += t;
    }
    if (tid < 16) g_bsum[tid] = x - v;
}

__global__ void scan3_kernel() {
    int b = blockIdx.x;
    int i = b * 1024 + threadIdx.x;
    if (i < NN) {
        int o = g_off[i] + g_bsum[b];
        g_off[i] = o;
        g_cur[i] = o;
    }
    if (i == 0) g_off[NN] = EE;
}

__global__ void scatter_kernel(const int* __restrict__ eidx) {
    int e = blockIdx.x * blockDim.x + threadIdx.x;
    if (e < EE) {
        int d = eidx[e];
        int pos = atomicAdd(&g_cur[d], 1);
        g_perm[pos] = e;
    }
}

// ---------------- kernel: per-edge weights via table lookup -----------------
__global__ __launch_bounds__(256) void edge_kernel(
        const float* __restrict__ edge_vec,
        const float* __restrict__ edge_attr,
        const float* __restrict__ Wattr,
        int l) {
    __shared__ float sWattr[13 * 32];
    const int tid = threadIdx.x;
    for (int i = tid; i < 416; i += 256) sWattr[i] = Wattr[l * 416 + i];
    __syncthreads();

    const int e = blockIdx.x * 256 + tid;
    float vx = edge_vec[3 * e + 0];
    float vy = edge_vec[3 * e + 1];
    float vz = edge_vec[3 * e + 2];
    float d = sqrtf(vx * vx + vy * vy + vz * vz + 1e-12f);

    float shv[9];
    compute_sh(vx, vy, vz, shv);
    if (l == 0) {
        #pragma unroll
        for (int k = 0; k < 9; k++) g_sh[e * 9 + k] = shv[k];
    }

    float ea[13];
    ea[0] = edge_attr[4 * e + 0];
    ea[1] = edge_attr[4 * e + 1];
    ea[2] = edge_attr[4 * e + 2];
    ea[3] = edge_attr[4 * e + 3];
    #pragma unroll
    for (int k = 0; k < 9; k++) ea[4 + k] = shv[k];

    // radial weight from table (lerp); d>=5 clamps to exact constant bin
    float u = d * TSCALE;
    if (u > (float)TBINS) u = (float)TBINS;
    int i0 = (int)u;
    float f = u - (float)i0;
    if (i0 >= TBINS) { i0 = TBINS - 1; f = 1.0f; }
    const float* r0 = &g_tab[((size_t)l * (TBINS + 1) + i0) * 32];

    float wr[32];
    #pragma unroll
    for (int q = 0; q < 8; q++) {
        float4 a = *(const float4*)(r0 + q * 4);
        float4 b = *(const float4*)(r0 + 32 + q * 4);
        wr[4 * q + 0] = a.x + f * (b.x - a.x);
        wr[4 * q + 1] = a.y + f * (b.y - a.y);
        wr[4 * q + 2] = a.z + f * (b.z - a.z);
        wr[4 * q + 3] = a.w + f * (b.w - a.w);
    }

    float4* outp4 = (float4*)(g_w + (size_t)e * 32);
    #pragma unroll
    for (int q = 0; q < 8; q++) {
        float aw0 = 0.f, aw1 = 0.f, aw2 = 0.f, aw3 = 0.f;
        #pragma unroll
        for (int i = 0; i < 13; i++) {
            const float* wa = &sWattr[i * 32 + 4 * q];
            float ei = ea[i];
            aw0 += ei * wa[0];
            aw1 += ei * wa[1];
            aw2 += ei * wa[2];
            aw3 += ei * wa[3];
        }
        float4 o;
        o.x = wr[4 * q + 0] * aw0;
        o.y = wr[4 * q + 1] * aw1;
        o.z = wr[4 * q + 2] * aw2;
        o.w = wr[4 * q + 3] * aw3;
        outp4[q] = o;
    }
}

// ---------------- fused aggregate + node update (ping-pong, race-free) ------
// 288 threads = 4 nodes x 72 (9k x 8c4). Reads xin only; writes xout only.
__global__ __launch_bounds__(288) void aggnode_kernel(
        const int* __restrict__ eidx,
        const float* __restrict__ node_attr,
        const float* __restrict__ Wself,
        const float* __restrict__ Wout,
        const float* __restrict__ xin,
        float* __restrict__ xout,
        int l) {
    __shared__ float sWs[1024], sWo[1024];
    __shared__ float sx[4][9][32];
    __shared__ float sagg[4][9][32];
    __shared__ float sval[4][32];

    int t = threadIdx.x;
    for (int i = t; i < 1024; i += 288) {
        sWs[i] = Wself[l * 1024 + i];
        sWo[i] = Wout[l * 1024 + i];
    }

    int sub = t / 72;
    int r = t - sub * 72;
    int k = r >> 3;
    int c4 = r & 7;
    int n = blockIdx.x * 4 + sub;

    *(float4*)&sx[sub][k][c4 * 4] =
        *(const float4*)(xin + (size_t)n * 288 + k * 32 + c4 * 4);

    int j0 = g_off[n];
    int j1 = g_off[n + 1];
    float4 acc = make_float4(0.f, 0.f, 0.f, 0.f);
    #pragma unroll 2
    for (int j = j0; j < j1; j++) {
        int e = g_perm[j];
        int src = eidx[EE + e];
        float s = g_sh[e * 9 + k];
        float4 w4 = *(const float4*)(g_w + (size_t)e * 32 + c4 * 4);
        float4 xv = *(const float4*)(xin + (size_t)src * 288 + k * 32 + c4 * 4);
        acc.x = fmaf(xv.x, s * w4.x, acc.x);
        acc.y = fmaf(xv.y, s * w4.y, acc.y);
        acc.z = fmaf(xv.z, s * w4.z, acc.z);
        acc.w = fmaf(xv.w, s * w4.w, acc.w);
    }
    *(float4*)&sagg[sub][k][c4 * 4] = acc;
    __syncthreads();

    // phase 2: t -> (k2, d)
    int k2 = t >> 5;
    int d = t & 31;
    float vals[4];
    #pragma unroll
    for (int s2 = 0; s2 < 4; s2++) {
        float accS = 0.0f, accA = 0.0f;
        #pragma unroll
        for (int c = 0; c < 32; c++) {
            accS += sx[s2][k2][c] * sWs[c * 32 + d];
            accA += sagg[s2][k2][c] * sWo[c * 32 + d];
        }
        float val = node_attr[blockIdx.x * 4 + s2] * accS + accA;
        vals[s2] = val;
        if (k2 == 0) sval[s2][d] = val;
    }
    __syncthreads();
    #pragma unroll
    for (int s2 = 0; s2 < 4; s2++) {
        float s = sval[s2][d];
        float sig = __fdividef(1.0f, 1.0f + __expf(-s));
        float res = (k2 == 0) ? s * sig : vals[s2] * sig;
        xout[((size_t)(blockIdx.x * 4 + s2) * 9 + k2) * 32 + d] = res;
    }
}

// ---------------- output reduction ------------------------------------------
__global__ void zero_kernel(float* __restrict__ p, int n) {
    int i = blockIdx.x * blockDim.x + threadIdx.x;
    if (i < n) p[i] = 0.0f;
}

__global__ void out_kernel(const int* __restrict__ batch,
                           const float* __restrict__ xfin,
                           float* __restrict__ out) {
    int t = threadIdx.x;        // 288 threads: output element (c,k)
    int c = t / 9;
    int k = t % 9;
    int n0 = blockIdx.x * 64;
    int n1 = n0 + 64;
    if (n1 > NN) n1 = NN;
    float acc = 0.0f;
    int curg = batch[n0];
    const float INVS400 = 0.05f;  // 1/sqrt(400)
    for (int n = n0; n < n1; n++) {
        int g = batch[n];
        if (g != curg) {
            atomicAdd(&out[curg * 288 + c * 9 + k], acc * INVS400);
            acc = 0.0f;
            curg = g;
        }
        acc += xfin[(n * SHD + k) * CC + c];
    }
    atomicAdd(&out[curg * 288 + c * 9 + k], acc * INVS400);
}

// ---------------- launch ----------------------------------------------------
extern "C" void kernel_launch(void* const* d_in, const int* in_sizes, int n_in,
                              void* d_out, int out_size) {
    const float* node_input = (const float*)d_in[0];
    const float* node_attr  = (const float*)d_in[1];
    const float* edge_vec   = (const float*)d_in[2];
    const float* edge_attr  = (const float*)d_in[3];
    const float* W1         = (const float*)d_in[4];
    const float* b1         = (const float*)d_in[5];
    const float* W2         = (const float*)d_in[6];
    const float* Wattr      = (const float*)d_in[7];
    const float* Wself      = (const float*)d_in[8];
    const float* Wout       = (const float*)d_in[9];
    const int*   eidx       = (const int*)d_in[10];
    const int*   batch      = (const int*)d_in[11];
    float* out = (float*)d_out;

    float* bufA; cudaGetSymbolAddress((void**)&bufA, g_bufA);
    float* bufB; cudaGetSymbolAddress((void**)&bufB, g_bufB);

    {
        int n = NN * CC * SHD;
        tin_kernel<<<(n + 255) / 256, 256>>>(node_input);
    }

    {
        dim3 g((TBINS + 1 + 127) / 128, NLAYERS);
        tab_kernel<<<g, 128>>>(W1, b1, W2);
    }

    zero_cnt_kernel<<<(NN + 255) / 256, 256>>>();
    hist_kernel<<<EE / 256, 256>>>(eidx);
    scan1_kernel<<<16, 1024>>>();
    scan2_kernel<<<1, 32>>>();
    scan3_kernel<<<16, 1024>>>();
    scatter_kernel<<<EE / 256, 256>>>(eidx);

    float* xin = bufA;
    float* xout = bufB;
    for (int l = 0; l < NLAYERS; l++) {
        edge_kernel<<<EE / 256, 256>>>(edge_vec, edge_attr, Wattr, l);
        aggnode_kernel<<<NN / 4, 288>>>(eidx, node_attr, Wself, Wout, xin, xout, l);
        float* tmp = xin; xin = xout; xout = tmp;
    }

    zero_kernel<<<(out_size + 255) / 256, 256>>>(out, out_size);
    out_kernel<<<(NN + 63) / 64, 288>>>(batch, xin, out);
}

// round 8
// speedup vs baseline: 1.4485x; 1.2259x over previous
#include <cuda_runtime.h>
#include <cstdint>

#define NN 16000
#define EE 512000
#define CC 32
#define SHD 9
#define NLAYERS 3
#define NGRAPHS 40
#define TBINS 2200          // bins over [0,5]; knots 5k/11 align at i=200k
#define TSCALE 440.0f       // TBINS/5

// ---------------- device scratch --------------------------------------------
__device__ float g_bufA[NN * SHD * CC];                  // node state ping (18.4 MB)
__device__ float g_bufB[NN * SHD * CC];                  // node state pong (18.4 MB)
__device__ float g_w[(size_t)EE * CC];                   // per-edge weights, PERMUTED (65.5 MB)
__device__ float g_shp[EE * SHD];                        // sph harmonics, PERMUTED (18.4 MB)
__device__ float g_vecp[EE * 3];                         // edge_vec, PERMUTED (6 MB)
__device__ float g_attrp[EE * 4];                        // edge_attr, PERMUTED (8 MB)
__device__ int   g_srcp[EE];                             // src node, PERMUTED (2 MB)
__device__ float g_tab[NLAYERS * (TBINS + 1) * CC];      // radial tables (0.85 MB)
__device__ int   g_cnt[NN];
__device__ int   g_off[NN + 1];
__device__ int   g_cur[NN];
__device__ int   g_bsum[16];

// ---------------- helpers ---------------------------------------------------
__device__ __forceinline__ float fast_silu(float x) {
    return __fdividef(x, 1.0f + __expf(-x));
}

__device__ __forceinline__ void compute_sh(float vx, float vy, float vz, float* shv) {
    float r2 = vx * vx + vy * vy + vz * vz + 1e-12f;
    float rinv = rsqrtf(r2);
    float x = vx * rinv, y = vy * rinv, z = vz * rinv;
    const float s3    = 1.7320508075688772f;
    const float s15   = 3.872983346207417f;
    const float s5_4  = 1.118033988749895f;    // sqrt(5)/2
    const float s15_4 = 1.9364916731037085f;   // sqrt(15)/2
    shv[0] = 1.0f;
    shv[1] = s3 * x;
    shv[2] = s3 * y;
    shv[3] = s3 * z;
    shv[4] = s15 * x * y;
    shv[5] = s15 * y * z;
    shv[6] = s5_4 * (3.0f * z * z - 1.0f);
    shv[7] = s15 * z * x;
    shv[8] = s15_4 * (x * x - y * y);
}

__device__ __forceinline__ void compute_emb(float d, float* emb) {
    const float stepinv = 11.0f / 5.0f;
    const float SQNB = 3.1622776601683795f;   // sqrt(10)
    const float HPI = 1.5707963267948966f;
    #pragma unroll
    for (int i = 0; i < 10; i++) {
        float center = (5.0f / 11.0f) * (float)(i + 1);
        float diff = (d - center) * stepinv;
        float v = 0.0f;
        if (diff > -1.0f && diff < 1.0f) v = __cosf(HPI * diff) * SQNB;
        emb[i] = v;
    }
}

// ---------------- kernel: transpose node_input (coalesced both sides) -------
__global__ __launch_bounds__(288) void tin_kernel(const float* __restrict__ node_input) {
    __shared__ float sm[288];
    int n = blockIdx.x;
    int t = threadIdx.x;
    sm[t] = node_input[n * 288 + t];          // [c][k], linear
    __syncthreads();
    int k = t >> 5, c = t & 31;
    g_bufA[(n * SHD + k) * CC + c] = sm[c * SHD + k];
}

// ---------------- radial table build (all layers) ---------------------------
__global__ void tab_kernel(const float* __restrict__ W1,
                           const float* __restrict__ b1,
                           const float* __restrict__ W2) {
    int bin = blockIdx.x * blockDim.x + threadIdx.x;
    int l = blockIdx.y;
    if (bin > TBINS) return;
    float d = (float)bin * (5.0f / (float)TBINS);
    float emb[10];
    compute_emb(d, emb);
    float w[32];
    #pragma unroll
    for (int c = 0; c < 32; c++) w[c] = 0.0f;
    for (int j = 0; j < 100; j++) {
        float h = b1[l * 100 + j];
        #pragma unroll
        for (int i = 0; i < 10; i++) h += emb[i] * W1[l * 1000 + i * 100 + j];
        h = fast_silu(h);
        const float* w2r = &W2[l * 3200 + j * 32];
        #pragma unroll
        for (int c = 0; c < 32; c++) w[c] += h * w2r[c];
    }
    const float INVS32 = 0.17677669529663687f;  // fold 1/sqrt(32)
    float* out = &g_tab[((size_t)l * (TBINS + 1) + bin) * 32];
    #pragma unroll
    for (int c = 0; c < 32; c++) out[c] = w[c] * INVS32;
}

// ---------------- sort-by-dst pipeline --------------------------------------
__global__ void zero_cnt_kernel() {
    int i = blockIdx.x * blockDim.x + threadIdx.x;
    if (i < NN) g_cnt[i] = 0;
}

__global__ void hist_kernel(const int* __restrict__ eidx) {
    int e = blockIdx.x * blockDim.x + threadIdx.x;
    if (e < EE) atomicAdd(&g_cnt[eidx[e]], 1);
}

__global__ void scan1_kernel() {
    __shared__ int wsum[32];
    int tid = threadIdx.x;
    int b = blockIdx.x;
    int i = b * 1024 + tid;
    int v = (i < NN) ? g_cnt[i] : 0;
    int lane = tid & 31, wid = tid >> 5;
    int x = v;
    #pragma unroll
    for (int o = 1; o < 32; o <<= 1) {
        int t = __shfl_up_sync(0xffffffffu, x, o);
        if (lane >= o) x += t;
    }
    if (lane == 31) wsum[wid] = x;
    __syncthreads();
    if (wid == 0) {
        int y = wsum[lane];
        #pragma unroll
        for (int o = 1; o < 32; o <<= 1) {
            int t = __shfl_up_sync(0xffffffffu, y, o);
            if (lane >= o) y += t;
        }
        wsum[lane] = y;
    }
    __syncthreads();
    int incl = x + ((wid > 0) ? wsum[wid - 1] : 0);
    if (i < NN) g_off[i] = incl - v;
    if (tid == 1023) g_bsum[b] = incl;
}

__global__ void scan2_kernel() {
    int tid = threadIdx.x;
    int v = (tid < 16) ? g_bsum[tid] : 0;
    int x = v;
    #pragma unroll
    for (int o = 1; o < 32; o <<= 1) {
        int t = __shfl_up_sync(0xffffffffu, x, o);
        if (tid >= o) x += t;
    }
    if (tid < 16) g_bsum[tid] = x - v;
}

__global__ void scan3_kernel() {
    int b = blockIdx.x;
    int i = b * 1024 + threadIdx.x;
    if (i < NN) {
        int o = g_off[i] + g_bsum[b];
        g_off[i] = o;
        g_cur[i] = o;
    }
    if (i == 0) g_off[NN] = EE;
}

// scatter: assign permuted slot AND materialize permuted edge payload
__global__ void scatter_kernel(const int* __restrict__ eidx,
                               const float* __restrict__ edge_vec,
                               const float* __restrict__ edge_attr) {
    int e = blockIdx.x * blockDim.x + threadIdx.x;
    if (e < EE) {
        int d = eidx[e];
        float v0 = edge_vec[3 * e + 0];
        float v1 = edge_vec[3 * e + 1];
        float v2 = edge_vec[3 * e + 2];
        float4 a = *(const float4*)(edge_attr + 4 * e);
        int s = eidx[EE + e];
        int pos = atomicAdd(&g_cur[d], 1);
        g_srcp[pos] = s;
        g_vecp[3 * pos + 0] = v0;
        g_vecp[3 * pos + 1] = v1;
        g_vecp[3 * pos + 2] = v2;
        *(float4*)(g_attrp + 4 * pos) = a;
    }
}

// ---------------- per-edge weights (fully streaming, permuted order) --------
__global__ __launch_bounds__(256) void edge_kernel(
        const float* __restrict__ Wattr,
        int l) {
    __shared__ float sWattr[13 * 32];
    const int tid = threadIdx.x;
    for (int i = tid; i < 416; i += 256) sWattr[i] = Wattr[l * 416 + i];
    __syncthreads();

    const int p = blockIdx.x * 256 + tid;
    float vx = g_vecp[3 * p + 0];
    float vy = g_vecp[3 * p + 1];
    float vz = g_vecp[3 * p + 2];
    float d = sqrtf(vx * vx + vy * vy + vz * vz + 1e-12f);

    float shv[9];
    compute_sh(vx, vy, vz, shv);
    if (l == 0) {
        #pragma unroll
        for (int k = 0; k < 9; k++) g_shp[p * 9 + k] = shv[k];
    }

    float ea[13];
    float4 a4 = *(const float4*)(g_attrp + 4 * p);
    ea[0] = a4.x; ea[1] = a4.y; ea[2] = a4.z; ea[3] = a4.w;
    #pragma unroll
    for (int k = 0; k < 9; k++) ea[4 + k] = shv[k];

    // radial weight from table (lerp); d>=5 clamps to exact constant bin
    float u = d * TSCALE;
    if (u > (float)TBINS) u = (float)TBINS;
    int i0 = (int)u;
    float f = u - (float)i0;
    if (i0 >= TBINS) { i0 = TBINS - 1; f = 1.0f; }
    const float* r0 = &g_tab[((size_t)l * (TBINS + 1) + i0) * 32];

    float wr[32];
    #pragma unroll
    for (int q = 0; q < 8; q++) {
        float4 a = *(const float4*)(r0 + q * 4);
        float4 b = *(const float4*)(r0 + 32 + q * 4);
        wr[4 * q + 0] = a.x + f * (b.x - a.x);
        wr[4 * q + 1] = a.y + f * (b.y - a.y);
        wr[4 * q + 2] = a.z + f * (b.z - a.z);
        wr[4 * q + 3] = a.w + f * (b.w - a.w);
    }

    float4* outp4 = (float4*)(g_w + (size_t)p * 32);
    #pragma unroll
    for (int q = 0; q < 8; q++) {
        float aw0 = 0.f, aw1 = 0.f, aw2 = 0.f, aw3 = 0.f;
        #pragma unroll
        for (int i = 0; i < 13; i++) {
            const float* wa = &sWattr[i * 32 + 4 * q];
            float ei = ea[i];
            aw0 += ei * wa[0];
            aw1 += ei * wa[1];
            aw2 += ei * wa[2];
            aw3 += ei * wa[3];
        }
        float4 o;
        o.x = wr[4 * q + 0] * aw0;
        o.y = wr[4 * q + 1] * aw1;
        o.z = wr[4 * q + 2] * aw2;
        o.w = wr[4 * q + 3] * aw3;
        outp4[q] = o;
    }
}

// ---------------- fused aggregate + node update (streaming payload) ---------
// 288 threads = 4 nodes x 72 (9k x 8c4). Edge payload sequential; x-gather in L2.
// Software-pipelined: prefetch next src/sh while computing current edge.
__global__ __launch_bounds__(288) void aggnode_kernel(
        const float* __restrict__ node_attr,
        const float* __restrict__ Wself,
        const float* __restrict__ Wout,
        const float* __restrict__ xin,
        float* __restrict__ xout,
        int l) {
    __shared__ float sWs[1024], sWo[1024];
    __shared__ float sx[4][9][32];
    __shared__ float sagg[4][9][32];
    __shared__ float sval[4][32];

    int t = threadIdx.x;
    for (int i = t; i < 1024; i += 288) {
        sWs[i] = Wself[l * 1024 + i];
        sWo[i] = Wout[l * 1024 + i];
    }

    int sub = t / 72;
    int r = t - sub * 72;
    int k = r >> 3;
    int c4 = r & 7;
    int n = blockIdx.x * 4 + sub;

    *(float4*)&sx[sub][k][c4 * 4] =
        *(const float4*)(xin + (size_t)n * 288 + k * 32 + c4 * 4);

    int j0 = g_off[n];
    int j1 = g_off[n + 1];
    float4 acc = make_float4(0.f, 0.f, 0.f, 0.f);

    if (j0 < j1) {
        // prologue: fetch edge j0
        int src0 = g_srcp[j0];
        float s0 = g_shp[j0 * 9 + k];
        float4 w0 = *(const float4*)(g_w + (size_t)j0 * 32 + c4 * 4);
        for (int j = j0; j < j1 - 1; j++) {
            // prefetch j+1 (independent of current compute)
            int src1 = g_srcp[j + 1];
            float s1 = g_shp[(j + 1) * 9 + k];
            float4 w1 = *(const float4*)(g_w + (size_t)(j + 1) * 32 + c4 * 4);
            float4 xv = *(const float4*)(xin + (size_t)src0 * 288 + k * 32 + c4 * 4);
            acc.x = fmaf(xv.x, s0 * w0.x, acc.x);
            acc.y = fmaf(xv.y, s0 * w0.y, acc.y);
            acc.z = fmaf(xv.z, s0 * w0.z, acc.z);
            acc.w = fmaf(xv.w, s0 * w0.w, acc.w);
            src0 = src1; s0 = s1; w0 = w1;
        }
        float4 xv = *(const float4*)(xin + (size_t)src0 * 288 + k * 32 + c4 * 4);
        acc.x = fmaf(xv.x, s0 * w0.x, acc.x);
        acc.y = fmaf(xv.y, s0 * w0.y, acc.y);
        acc.z = fmaf(xv.z, s0 * w0.z, acc.z);
        acc.w = fmaf(xv.w, s0 * w0.w, acc.w);
    }
    *(float4*)&sagg[sub][k][c4 * 4] = acc;
    __syncthreads();

    // phase 2: t -> (k2, d)
    int k2 = t >> 5;
    int d = t & 31;
    float vals[4];
    #pragma unroll
    for (int s2 = 0; s2 < 4; s2++) {
        float accS = 0.0f, accA = 0.0f;
        #pragma unroll
        for (int c = 0; c < 32; c++) {
            accS += sx[s2][k2][c] * sWs[c * 32 + d];
            accA += sagg[s2][k2][c] * sWo[c * 32 + d];
        }
        float val = node_attr[blockIdx.x * 4 + s2] * accS + accA;
        vals[s2] = val;
        if (k2 == 0) sval[s2][d] = val;
    }
    __syncthreads();
    #pragma unroll
    for (int s2 = 0; s2 < 4; s2++) {
        float s = sval[s2][d];
        float sig = __fdividef(1.0f, 1.0f + __expf(-s));
        float res = (k2 == 0) ? s * sig : vals[s2] * sig;
        xout[((size_t)(blockIdx.x * 4 + s2) * 9 + k2) * 32 + d] = res;
    }
}

// ---------------- output reduction ------------------------------------------
__global__ void zero_kernel(float* __restrict__ p, int n) {
    int i = blockIdx.x * blockDim.x + threadIdx.x;
    if (i < n) p[i] = 0.0f;
}

__global__ __launch_bounds__(288) void out_kernel(const int* __restrict__ batch,
                                                  const float* __restrict__ xfin,
                                                  float* __restrict__ out) {
    int t = threadIdx.x;
    int k = t >> 5;             // warp reads contiguous c
    int c = t & 31;
    int n0 = blockIdx.x * 64;
    int n1 = n0 + 64;
    if (n1 > NN) n1 = NN;
    float acc = 0.0f;
    int curg = batch[n0];
    const float INVS400 = 0.05f;  // 1/sqrt(400)
    for (int n = n0; n < n1; n++) {
        int g = batch[n];
        if (g != curg) {
            atomicAdd(&out[curg * 288 + c * 9 + k], acc * INVS400);
            acc = 0.0f;
            curg = g;
        }
        acc += xfin[(n * SHD + k) * CC + c];
    }
    atomicAdd(&out[curg * 288 + c * 9 + k], acc * INVS400);
}

// ---------------- launch ----------------------------------------------------
extern "C" void kernel_launch(void* const* d_in, const int* in_sizes, int n_in,
                              void* d_out, int out_size) {
    const float* node_input = (const float*)d_in[0];
    const float* node_attr  = (const float*)d_in[1];
    const float* edge_vec   = (const float*)d_in[2];
    const float* edge_attr  = (const float*)d_in[3];
    const float* W1         = (const float*)d_in[4];
    const float* b1         = (const float*)d_in[5];
    const float* W2         = (const float*)d_in[6];
    const float* Wattr      = (const float*)d_in[7];
    const float* Wself      = (const float*)d_in[8];
    const float* Wout       = (const float*)d_in[9];
    const int*   eidx       = (const int*)d_in[10];
    const int*   batch      = (const int*)d_in[11];
    float* out = (float*)d_out;

    float* bufA; cudaGetSymbolAddress((void**)&bufA, g_bufA);
    float* bufB; cudaGetSymbolAddress((void**)&bufB, g_bufB);

    tin_kernel<<<NN, 288>>>(node_input);

    {
        dim3 g((TBINS + 1 + 127) / 128, NLAYERS);
        tab_kernel<<<g, 128>>>(W1, b1, W2);
    }

    zero_cnt_kernel<<<(NN + 255) / 256, 256>>>();
    hist_kernel<<<EE / 256, 256>>>(eidx);
    scan1_kernel<<<16, 1024>>>();
    scan2_kernel<<<1, 32>>>();
    scan3_kernel<<<16, 1024>>>();
    scatter_kernel<<<EE / 256, 256>>>(eidx, edge_vec, edge_attr);

    float* xin = bufA;
    float* xout = bufB;
    for (int l = 0; l < NLAYERS; l++) {
        edge_kernel<<<EE / 256, 256>>>(Wattr, l);
        aggnode_kernel<<<NN / 4, 288>>>(node_attr, Wself, Wout, xin, xout, l);
        float* tmp = xin; xin = xout; xout = tmp;
    }

    zero_kernel<<<(out_size + 255) / 256, 256>>>(out, out_size);
    out_kernel<<<(NN + 63) / 64, 288>>>(batch, xin, out);
}